// round 2
// baseline (speedup 1.0000x reference)
#include <cuda_runtime.h>
#include <cuda_bf16.h>
#include <cstdint>

// ---------------- problem constants ----------------
#define BB    8192
#define TT    406
#define DD    10
#define PP    64
#define KD    (TT*DD)          // 4060
#define KS    4                // k-splits
#define BTILE 256
#define NBT   (BB/BTILE)       // 32
#define TC    7                // t per chunk (58*7 = 406 exactly)
#define NCH   (TT/TC)          // 58
#define KC    (TC*(DD+1))      // 77 augmented-K slots per chunk
#define ASTR  (BTILE+4)        // 260 (mult of 4 for float4)
#define CSTR  (PP+4)           // 68

#define SMEM_FLOATS (KC*ASTR + KC*CSTR + BTILE*8)
#define SMEM_BYTES  (SMEM_FLOATS*4)

// ---------------- scratch (device globals, no alloc) ----------------
__device__ float g_csq[PP*TT];             // sum_d c^2 per (p,t)
__device__ float g_partial[KS][BB][PP];    // -2*cross + sq_p partials
__device__ float g_sqx[KS][BB];            // sum m*x^2 partials

// ---------------- f32x2 helpers ----------------
__device__ __forceinline__ unsigned long long pack2(float lo, float hi) {
    unsigned long long r;
    asm("mov.b64 %0, {%1, %2};" : "=l"(r) : "r"(__float_as_uint(lo)), "r"(__float_as_uint(hi)));
    return r;
}
__device__ __forceinline__ void unpack2(unsigned long long v, float &lo, float &hi) {
    unsigned int a, b;
    asm("mov.b64 {%0, %1}, %2;" : "=r"(a), "=r"(b) : "l"(v));
    lo = __uint_as_float(a); hi = __uint_as_float(b);
}
__device__ __forceinline__ void ffma2(unsigned long long &d, unsigned long long a, unsigned long long b) {
    asm("fma.rn.f32x2 %0, %1, %2, %0;" : "+l"(d) : "l"(a), "l"(b));
}

// ---------------- kernel 0: csq[p][t] = sum_d c^2 ----------------
__global__ void prep_csq(const float* __restrict__ proto) {
    int i = blockIdx.x * blockDim.x + threadIdx.x;
    if (i < PP * TT) {
        int p = i / TT, t = i - p * TT;
        const float* c = proto + (size_t)p * KD + t * DD;
        float s = 0.f;
        #pragma unroll
        for (int d = 0; d < DD; d++) s = fmaf(c[d], c[d], s);
        g_csq[i] = s;
    }
}

// ---------------- kernel 1: fused masked-distance GEMM + copies ----------------
// grid = NBT*KS = 128 blocks, 256 threads. Block (bt, ks) owns 256 b-rows and
// one t-range; computes partial (-2*cross + sq_p) for 256x64, partial sq_x,
// and streams the input_seq / mask copies to the output while staging.
__global__ void __launch_bounds__(256, 1) main_kernel(
    const float* __restrict__ x, const float* __restrict__ mask,
    const float* __restrict__ proto,
    float* __restrict__ out_xcopy, float* __restrict__ out_mask)
{
    extern __shared__ float smem[];
    float* a_s = smem;                       // [KC][ASTR] transposed mx tile (+ mask slots)
    float* c_s = a_s + KC * ASTR;            // [KC][CSTR] transposed -2c tile (+ csq slots)
    float* m_s = c_s + KC * CSTR;            // [BTILE][8] mask tile

    const int tid = threadIdx.x;
    const int bt  = blockIdx.x >> 2;
    const int ks  = blockIdx.x & 3;
    const int b0  = bt * BTILE;
    const int ch0 = (NCH * ks) / KS;
    const int ch1 = (NCH * (ks + 1)) / KS;

    const int tx = tid & 7;        // p-group
    const int ty = tid >> 3;       // b-group
    const int p8 = tx * 8;
    const int b8 = ty * 8;

    unsigned long long acc[8][4];
    #pragma unroll
    for (int i = 0; i < 8; i++)
        #pragma unroll
        for (int j = 0; j < 4; j++) acc[i][j] = 0ULL;
    float sqx = 0.f;

    for (int ch = ch0; ch < ch1; ++ch) {
        const int t0 = ch * TC;
        __syncthreads();   // previous GEMM/sqx reads done before restage

        // ---- stage mask tile (+ fused mask copy, + mask slots of a_s) ----
        for (int i = tid; i < BTILE * TC; i += 256) {
            int r = i / TC, c = i - r * TC;
            float m = mask[(size_t)(b0 + r) * TT + t0 + c];
            m_s[r * 8 + c] = m;
            out_mask[(size_t)(b0 + r) * TT + t0 + c] = m;
            a_s[(c * 11 + 10) * ASTR + r] = m;
        }
        // ---- stage prototype side: -2c and csq slots ----
        for (int i = tid; i < PP * TC * DD; i += 256) {
            int r = i / (TC * DD), c = i - r * (TC * DD);
            float v = proto[(size_t)r * KD + t0 * DD + c];
            int tt = c / DD, dd = c - tt * DD;
            c_s[(tt * 11 + dd) * CSTR + r] = -2.0f * v;
        }
        for (int i = tid; i < PP * TC; i += 256) {
            int r = i / TC, c = i - r * TC;
            c_s[(c * 11 + 10) * CSTR + r] = g_csq[r * TT + t0 + c];
        }
        __syncthreads();   // m_s ready

        // ---- stage x side: masked, transposed (+ fused input_seq copy) ----
        for (int i = tid; i < BTILE * TC * DD; i += 256) {
            int r = i / (TC * DD), c = i - r * (TC * DD);
            size_t gi = (size_t)(b0 + r) * KD + t0 * DD + c;
            float v = x[gi];
            out_xcopy[gi] = v;
            int tt = c / DD, dd = c - tt * DD;
            a_s[(tt * 11 + dd) * ASTR + r] = v * m_s[r * 8 + tt];
        }
        __syncthreads();   // tiles ready

        // ---- sq_x partial: mask is 0/1 so sum m*x^2 = sum (m*x)^2 ----
        {
            float s = 0.f;
            #pragma unroll
            for (int tt = 0; tt < TC; tt++)
                #pragma unroll
                for (int dd = 0; dd < DD; dd++) {
                    float v = a_s[(tt * 11 + dd) * ASTR + tid];
                    s = fmaf(v, v, s);
                }
            sqx += s;
        }

        // ---- inner GEMM: 8b x 8p per thread, packed f32x2 FMAs ----
        #pragma unroll 7
        for (int k = 0; k < KC; k++) {
            const float4 aA = *(const float4*)(a_s + k * ASTR + b8);
            const float4 aB = *(const float4*)(a_s + k * ASTR + b8 + 4);
            const float4 cA = *(const float4*)(c_s + k * CSTR + p8);
            const float4 cB = *(const float4*)(c_s + k * CSTR + p8 + 4);
            unsigned long long cp0 = pack2(cA.x, cA.y);
            unsigned long long cp1 = pack2(cA.z, cA.w);
            unsigned long long cp2 = pack2(cB.x, cB.y);
            unsigned long long cp3 = pack2(cB.z, cB.w);
            float av[8] = {aA.x, aA.y, aA.z, aA.w, aB.x, aB.y, aB.z, aB.w};
            #pragma unroll
            for (int i = 0; i < 8; i++) {
                unsigned long long as = pack2(av[i], av[i]);
                ffma2(acc[i][0], as, cp0);
                ffma2(acc[i][1], as, cp1);
                ffma2(acc[i][2], as, cp2);
                ffma2(acc[i][3], as, cp3);
            }
        }
    }

    // ---- write partials ----
    g_sqx[ks][b0 + tid] = sqx;
    #pragma unroll
    for (int i = 0; i < 8; i++) {
        float2* dst = (float2*)&g_partial[ks][b0 + b8 + i][p8];
        #pragma unroll
        for (int j = 0; j < 4; j++) {
            float lo, hi; unpack2(acc[i][j], lo, hi);
            dst[j] = make_float2(lo, hi);
        }
    }
}

// ---------------- kernel 2: combine, argmin, outputs, gather ----------------
__global__ void __launch_bounds__(256) finalize_kernel(
    const float* __restrict__ proto, const int* __restrict__ label,
    float* __restrict__ out_seq, float* __restrict__ out_dist,
    float* __restrict__ out_idx, float* __restrict__ out_label)
{
    __shared__ int s_idx[8];
    const int tid = threadIdx.x, w = tid >> 5, lane = tid & 31;
    const int b = blockIdx.x * 8 + w;

    // phase 1: one warp per b — distances + first-occurrence argmin
    {
        float sx = g_sqx[0][b] + g_sqx[1][b] + g_sqx[2][b] + g_sqx[3][b];
        float d0 = sx + g_partial[0][b][lane]      + g_partial[1][b][lane]
                      + g_partial[2][b][lane]      + g_partial[3][b][lane];
        float d1 = sx + g_partial[0][b][lane + 32] + g_partial[1][b][lane + 32]
                      + g_partial[2][b][lane + 32] + g_partial[3][b][lane + 32];
        out_dist[(size_t)b * PP + lane]      = d0;
        out_dist[(size_t)b * PP + lane + 32] = d1;

        float bd; int bp;
        if (d1 < d0) { bd = d1; bp = lane + 32; } else { bd = d0; bp = lane; }
        #pragma unroll
        for (int o = 16; o > 0; o >>= 1) {
            float od = __shfl_xor_sync(0xffffffffu, bd, o);
            int   op = __shfl_xor_sync(0xffffffffu, bp, o);
            if (od < bd || (od == bd && op < bp)) { bd = od; bp = op; }
        }
        if (lane == 0) {
            s_idx[w] = bp;
            out_idx[b]   = (float)bp;
            out_label[b] = (float)label[b];   // label input is int32 on device
        }
    }
    __syncthreads();

    // phase 2: block-wide gather output_seq = prototypes[idx] (float4 copy)
    const int bbase = blockIdx.x * 8;
    for (int ww = 0; ww < 8; ww++) {
        int idx = s_idx[ww];
        const float4* src = (const float4*)(proto + (size_t)idx * KD);
        float4* dst = (float4*)(out_seq + (size_t)(bbase + ww) * KD);
        for (int i = tid; i < KD / 4; i += 256) dst[i] = src[i];
    }
}

// ---------------- launch ----------------
extern "C" void kernel_launch(void* const* d_in, const int* in_sizes, int n_in,
                              void* d_out, int out_size) {
    const float* x     = (const float*)d_in[0];
    const int*   label = (const int*)d_in[1];      // int64 in reference -> int32 on device
    const float* mask  = (const float*)d_in[2];
    const float* proto = (const float*)d_in[3];
    float* out = (float*)d_out;

    const size_t o_seq   = 0;
    const size_t o_xcopy = (size_t)BB * KD;              // 33,259,520
    const size_t o_dist  = o_xcopy * 2;                  // 66,519,040
    const size_t o_idx   = o_dist + (size_t)BB * PP;     // 67,043,328
    const size_t o_label = o_idx + BB;
    const size_t o_mask  = o_label + BB;

    cudaFuncSetAttribute(main_kernel, cudaFuncAttributeMaxDynamicSharedMemorySize, SMEM_BYTES);

    prep_csq<<<(PP * TT + 255) / 256, 256>>>(proto);
    main_kernel<<<NBT * KS, 256, SMEM_BYTES>>>(x, mask, proto,
                                               out + o_xcopy, out + o_mask);
    finalize_kernel<<<BB / 8, 256>>>(proto, label,
                                     out + o_seq, out + o_dist,
                                     out + o_idx, out + o_label);
}

// round 4
// speedup vs baseline: 1.4594x; 1.4594x over previous
#include <cuda_runtime.h>
#include <cuda_bf16.h>
#include <cstdint>

// ---------------- problem constants ----------------
#define BB    8192
#define TT    406
#define DD    10
#define PP    64
#define KD    (TT*DD)            // 4060
#define MTILE 128
#define NMT   (BB/MTILE)         // 64
#define KSPL  2
#define TC8   8                  // t per chunk
#define NCHT  51                 // ceil(406/8)
#define CSPL0 26                 // chunks in split 0 -> t [0,208)
#define KCN   11                 // k-chunks (of 8) per chunk: 8t*11slots/8
#define ASTR  140                // A smem stride (floats)
#define BSTR  76                 // B smem stride (floats)
#define A_FLOATS (88*ASTR)       // 12320
#define B_FLOATS (88*BSTR)       // 6688
#define BUF_FLOATS (A_FLOATS + B_FLOATS)
#define SMEM_MAIN (2*BUF_FLOATS*4)   // 152064 bytes
#define MARGIN 4.0f

// ---------------- scratch (device globals, no alloc) ----------------
__device__ float g_csq[PP*TT];            // sum_d c^2 per (p,t)
__device__ float g_partial[KSPL][BB][PP]; // (-2*cross + sq_p) partials
__device__ float g_sqx[KSPL][BB];         // sum m*x^2 partials

__device__ __forceinline__ uint32_t tf32r(float v) {
    uint32_t r; asm("cvt.rna.tf32.f32 %0, %1;" : "=r"(r) : "f"(v)); return r;
}

// ---------------- kernel 0: csq[p][t] = sum_d c^2 ----------------
__global__ void prep_csq(const float* __restrict__ proto) {
    int i = blockIdx.x * blockDim.x + threadIdx.x;
    if (i < PP * TT) {
        int p = i / TT, t = i - p * TT;
        const float* c = proto + (size_t)p * KD + t * DD;
        float s = 0.f;
        #pragma unroll
        for (int d = 0; d < DD; d++) s = fmaf(c[d], c[d], s);
        g_csq[i] = s;
    }
}

// ---------------- kernel 1: TF32 mma.sync GEMM, fused copies ----------------
// grid = NMT*KSPL = 128 blocks, 256 threads. Block (mt, ks) owns 128 b-rows,
// one t-range. Computes partial (-2*cross + sq_p) via augmented-K (11 slots/t:
// 10 dims of (m*x | -2c) + (m | csq)). Fuses the mandatory x/mask output
// copies and exact-fp32 sq_x into the staging pass.
__global__ void __launch_bounds__(256, 1) main_kernel(
    const float* __restrict__ x, const float* __restrict__ mask,
    const float* __restrict__ proto,
    float* __restrict__ out_xcopy, float* __restrict__ out_mask)
{
    extern __shared__ float smem_f[];
    const int tid  = threadIdx.x;
    const int wid  = tid >> 5, lane = tid & 31;
    const int mt   = blockIdx.x >> 1;
    const int ks   = blockIdx.x & 1;
    const int b0   = mt * MTILE;
    const int c_beg = ks ? CSPL0 : 0;
    const int c_end = ks ? NCHT  : CSPL0;

    // staging roles
    const int ab = tid >> 1, ah = tid & 1;     // A: b-row, which 4-t half
    const int bp = tid >> 2, btg = tid & 3;    // B: p-row, which 2-t group
    // mma roles
    const int tig = lane & 3, grp = lane >> 2;
    const int wm = wid & 3, wn = wid >> 2;
    const int boff = wm * 32, noff = wn * 32;

    float acc[2][4][4];
    #pragma unroll
    for (int i = 0; i < 2; i++)
        #pragma unroll
        for (int j = 0; j < 4; j++)
            #pragma unroll
            for (int q = 0; q < 4; q++) acc[i][j][q] = 0.f;
    float sqx = 0.f;

    // register staging buffers
    float xr[4][10], mr[4];
    float cr[2][10], cq[2];

    auto ldg_chunk = [&](int c) {
        const int t0 = c * TC8;
        #pragma unroll
        for (int j = 0; j < 4; j++) {
            int t = t0 + ah * 4 + j;
            bool v = (t < TT);
            mr[j] = v ? mask[(size_t)(b0 + ab) * TT + t] : 0.f;
            const float2* xp = (const float2*)(x + ((size_t)(b0 + ab) * TT + t) * DD);
            #pragma unroll
            for (int q = 0; q < 5; q++) {
                float2 z = v ? xp[q] : make_float2(0.f, 0.f);
                xr[j][2*q] = z.x; xr[j][2*q+1] = z.y;
            }
        }
        #pragma unroll
        for (int j = 0; j < 2; j++) {
            int t = t0 + btg * 2 + j;
            bool v = (t < TT);
            const float2* cp = (const float2*)(proto + ((size_t)bp * TT + t) * DD);
            #pragma unroll
            for (int q = 0; q < 5; q++) {
                float2 z = v ? cp[q] : make_float2(0.f, 0.f);
                cr[j][2*q] = z.x; cr[j][2*q+1] = z.y;
            }
            cq[j] = v ? g_csq[bp * TT + t] : 0.f;
        }
    };

    auto sts_chunk = [&](int c) {
        float* a_s = smem_f + (c & 1) * BUF_FLOATS;
        float* b_s = a_s + A_FLOATS;
        const int t0 = c * TC8;
        #pragma unroll
        for (int j = 0; j < 4; j++) {
            int tloc = ah * 4 + j;
            int t = t0 + tloc;
            float m = mr[j];
            if (t < TT) {
                float2* xo = (float2*)(out_xcopy + ((size_t)(b0 + ab) * TT + t) * DD);
                #pragma unroll
                for (int q = 0; q < 5; q++)
                    xo[q] = make_float2(xr[j][2*q], xr[j][2*q+1]);
                out_mask[(size_t)(b0 + ab) * TT + t] = m;
            }
            #pragma unroll
            for (int s = 0; s < 10; s++) {
                float v = m * xr[j][s];
                sqx = fmaf(v, xr[j][s], sqx);   // m in {0,1}: m*x*x
                a_s[(tloc * 11 + s) * ASTR + ab] = __uint_as_float(tf32r(v));
            }
            a_s[(tloc * 11 + 10) * ASTR + ab] = m;   // 0/1 exact in tf32
        }
        #pragma unroll
        for (int j = 0; j < 2; j++) {
            int tloc = btg * 2 + j;
            #pragma unroll
            for (int s = 0; s < 10; s++)
                b_s[(tloc * 11 + s) * BSTR + bp] = __uint_as_float(tf32r(-2.f * cr[j][s]));
            b_s[(tloc * 11 + 10) * BSTR + bp] = __uint_as_float(tf32r(cq[j]));
        }
    };

    auto mma_chunk = [&](int c) {
        const float* a_s = smem_f + (c & 1) * BUF_FLOATS;
        const float* b_s = a_s + A_FLOATS;
        #pragma unroll
        for (int kc = 0; kc < KCN; kc++) {
            const int k0 = kc * 8;
            uint32_t af[2][4], bf[4][2];
            #pragma unroll
            for (int i = 0; i < 2; i++) {
                int rb = boff + i * 16 + grp;
                af[i][0] = __float_as_uint(a_s[(k0 + tig)     * ASTR + rb]);
                af[i][1] = __float_as_uint(a_s[(k0 + tig)     * ASTR + rb + 8]);
                af[i][2] = __float_as_uint(a_s[(k0 + 4 + tig) * ASTR + rb]);
                af[i][3] = __float_as_uint(a_s[(k0 + 4 + tig) * ASTR + rb + 8]);
            }
            #pragma unroll
            for (int j = 0; j < 4; j++) {
                int cp2 = noff + j * 8 + grp;
                bf[j][0] = __float_as_uint(b_s[(k0 + tig)     * BSTR + cp2]);
                bf[j][1] = __float_as_uint(b_s[(k0 + 4 + tig) * BSTR + cp2]);
            }
            #pragma unroll
            for (int i = 0; i < 2; i++)
                #pragma unroll
                for (int j = 0; j < 4; j++)
                    asm volatile(
                        "mma.sync.aligned.m16n8k8.row.col.f32.tf32.tf32.f32 "
                        "{%0,%1,%2,%3}, {%4,%5,%6,%7}, {%8,%9}, {%0,%1,%2,%3};"
                        : "+f"(acc[i][j][0]), "+f"(acc[i][j][1]),
                          "+f"(acc[i][j][2]), "+f"(acc[i][j][3])
                        : "r"(af[i][0]), "r"(af[i][1]), "r"(af[i][2]), "r"(af[i][3]),
                          "r"(bf[j][0]), "r"(bf[j][1]));
        }
    };

    // software pipeline: STS(c) -> sync -> LDG(c+1) -> MMA(c)
    ldg_chunk(c_beg);
    for (int c = c_beg; c < c_end; ++c) {
        sts_chunk(c);
        __syncthreads();
        if (c + 1 < c_end) ldg_chunk(c + 1);
        mma_chunk(c);
    }

    // sqx pair-combine (tid pairs share b-row ab) + store
    float sqt = sqx + __shfl_xor_sync(0xffffffffu, sqx, 1);
    if (!ah) g_sqx[ks][b0 + ab] = sqt;

    // epilogue: accumulators -> g_partial
    #pragma unroll
    for (int i = 0; i < 2; i++) {
        int rb = b0 + boff + i * 16 + grp;
        #pragma unroll
        for (int j = 0; j < 4; j++) {
            int cc = noff + j * 8 + 2 * tig;
            *(float2*)&g_partial[ks][rb][cc]     = make_float2(acc[i][j][0], acc[i][j][1]);
            *(float2*)&g_partial[ks][rb + 8][cc] = make_float2(acc[i][j][2], acc[i][j][3]);
        }
    }
}

// ---------------- kernel 2: combine, argmin (+exact rescore), outputs, gather ----------------
__global__ void __launch_bounds__(256) finalize_kernel(
    const float* __restrict__ x, const float* __restrict__ mask,
    const float* __restrict__ proto, const int* __restrict__ label,
    float* __restrict__ out_seq, float* __restrict__ out_dist,
    float* __restrict__ out_idx, float* __restrict__ out_label)
{
    __shared__ int s_idx[8];
    const int tid = threadIdx.x, w = tid >> 5, lane = tid & 31;
    const int b = blockIdx.x * 8 + w;

    {
        float sx = g_sqx[0][b] + g_sqx[1][b];
        float d0 = sx + g_partial[0][b][lane]      + g_partial[1][b][lane];
        float d1 = sx + g_partial[0][b][lane + 32] + g_partial[1][b][lane + 32];
        out_dist[(size_t)b * PP + lane]      = d0;
        out_dist[(size_t)b * PP + lane + 32] = d1;

        float bd; int bpick;
        if (d1 < d0) { bd = d1; bpick = lane + 32; } else { bd = d0; bpick = lane; }
        #pragma unroll
        for (int o = 16; o > 0; o >>= 1) {
            float od = __shfl_xor_sync(0xffffffffu, bd, o);
            int   op = __shfl_xor_sync(0xffffffffu, bpick, o);
            if (od < bd || (od == bd && op < bpick)) { bd = od; bpick = op; }
        }
        // candidates within MARGIN of tf32-min -> exact fp32 rescore if >1
        unsigned c0 = __ballot_sync(0xffffffffu, d0 < bd + MARGIN);
        unsigned c1 = __ballot_sync(0xffffffffu, d1 < bd + MARGIN);
        unsigned long long cm = ((unsigned long long)c1 << 32) | (unsigned long long)c0;
        int idx = bpick;
        if (__popcll(cm) > 1) {
            float best = 3.4e38f; int bi = PP;
            while (cm) {
                int p = __ffsll((long long)cm) - 1;
                cm &= cm - 1;
                float r = 0.f;
                const float* xrow = x + (size_t)b * KD;
                const float* crow = proto + (size_t)p * KD;
                for (int t = lane; t < TT; t += 32) {
                    float m = mask[(size_t)b * TT + t];
                    if (m != 0.f) {
                        const float* xp = xrow + t * DD;
                        const float* cp = crow + t * DD;
                        float dot = 0.f;
                        #pragma unroll
                        for (int d = 0; d < DD; d++) dot = fmaf(xp[d], cp[d], dot);
                        r += g_csq[p * TT + t] - 2.f * dot;
                    }
                }
                #pragma unroll
                for (int o = 16; o > 0; o >>= 1) r += __shfl_xor_sync(0xffffffffu, r, o);
                if (r < best) { best = r; bi = p; }   // ascending p: first-occurrence ties
            }
            idx = bi;
        }
        if (lane == 0) {
            s_idx[w] = idx;
            out_idx[b]   = (float)idx;
            out_label[b] = (float)label[b];
        }
    }
    __syncthreads();

    // gather output_seq = prototypes[idx]
    const int bbase = blockIdx.x * 8;
    for (int ww = 0; ww < 8; ww++) {
        int idx = s_idx[ww];
        const float4* src = (const float4*)(proto + (size_t)idx * KD);
        float4* dst = (float4*)(out_seq + (size_t)(bbase + ww) * KD);
        for (int i = tid; i < KD / 4; i += 256) dst[i] = src[i];
    }
}

// ---------------- launch ----------------
extern "C" void kernel_launch(void* const* d_in, const int* in_sizes, int n_in,
                              void* d_out, int out_size) {
    const float* x     = (const float*)d_in[0];
    const int*   label = (const int*)d_in[1];
    const float* mask  = (const float*)d_in[2];
    const float* proto = (const float*)d_in[3];
    float* out = (float*)d_out;

    const size_t o_seq   = 0;
    const size_t o_xcopy = (size_t)BB * KD;
    const size_t o_dist  = o_xcopy * 2;
    const size_t o_idx   = o_dist + (size_t)BB * PP;
    const size_t o_label = o_idx + BB;
    const size_t o_mask  = o_label + BB;

    cudaFuncSetAttribute(main_kernel, cudaFuncAttributeMaxDynamicSharedMemorySize, SMEM_MAIN);

    prep_csq<<<(PP * TT + 255) / 256, 256>>>(proto);
    main_kernel<<<NMT * KSPL, 256, SMEM_MAIN>>>(x, mask, proto,
                                                out + o_xcopy, out + o_mask);
    finalize_kernel<<<BB / 8, 256>>>(x, mask, proto, label,
                                     out + o_seq, out + o_dist,
                                     out + o_idx, out + o_label);
}

// round 5
// speedup vs baseline: 2.0555x; 1.4084x over previous
#include <cuda_runtime.h>
#include <cuda_bf16.h>
#include <cstdint>

// ---------------- problem constants ----------------
#define BB    8192
#define TT    406
#define DD    10
#define PP    64
#define KD    (TT*DD)            // 4060
#define MTILE 128
#define NMT   (BB/MTILE)         // 64
#define KSPL  2
#define TC8   8                  // t per chunk
#define NCHT  51                 // ceil(406/8) (t padded to 408)
#define CSPL0 26                 // chunks in split 0
#define SLOT  12                 // k-slots per t: 10 dims + (m|csq) + (sumsq|1)
#define KCN   12                 // k8-chunks per chunk (96/8)
#define TS    100                // tile stride (floats); 100 mod 32 = 4 -> conflict-free frags
#define MARGIN 4.0f

// smem layout (floats): msk[2][1024], then 2 x (A[128*100] + B[64*100])
#define MSK_F   1024
#define A_F     (MTILE*TS)       // 12800
#define B_F     (PP*TS)          // 6400
#define BUF_F   (A_F + B_F)      // 19200
#define SMEM_FLOATS (2*MSK_F + 2*BUF_F)
#define SMEM_MAIN   (SMEM_FLOATS*4)    // 161792 B

// ---------------- scratch (device globals, no alloc) ----------------
__device__ float g_csq[PP*TT];            // sum_d c^2 per (p,t)
__device__ float g_partial[KSPL][BB][PP]; // full-distance partials

__device__ __forceinline__ uint32_t tf32r(float v) {
    uint32_t r; asm("cvt.rna.tf32.f32 %0, %1;" : "=r"(r) : "f"(v)); return r;
}

// ---------------- kernel 0: csq[p][t] = sum_d c^2 ----------------
__global__ void prep_csq(const float* __restrict__ proto) {
    int i = blockIdx.x * blockDim.x + threadIdx.x;
    if (i < PP * TT) {
        int p = i / TT, t = i - p * TT;
        const float* c = proto + (size_t)p * KD + t * DD;
        float s = 0.f;
        #pragma unroll
        for (int d = 0; d < DD; d++) s = fmaf(c[d], c[d], s);
        g_csq[i] = s;
    }
}

// ---------------- kernel 1: TF32 mma.sync GEMM, coalesced staging ----------------
// grid = 128 blocks x 512 thr. Block (mt, ks): 128 b-rows, one t-range.
// Accumulators = full distance (sq_x folded in as k-slot 11).
__global__ void __launch_bounds__(512, 1) main_kernel(
    const float* __restrict__ x, const float* __restrict__ mask,
    const float* __restrict__ proto,
    float* __restrict__ out_xcopy, float* __restrict__ out_mask)
{
    extern __shared__ float sm[];
    float* msk_s = sm;                      // [2][1024]
    float* buf_s = sm + 2 * MSK_F;          // [2][A_F + B_F]

    const int tid = threadIdx.x;
    const int wid = tid >> 5, lane = tid & 31;
    const int mt  = blockIdx.x >> 1;
    const int ks  = blockIdx.x & 1;
    const int b0  = mt * MTILE;
    const int c_beg = ks ? CSPL0 : 0;
    const int c_end = ks ? NCHT  : CSPL0;

    // mma roles: 16 warps = 4m x 4n
    const int tig = lane & 3, grp = lane >> 2;
    const int wm = wid & 3, wn = wid >> 2;
    const int boff = wm * 32, noff = wn * 16;

    float acc[2][2][4];
    #pragma unroll
    for (int i = 0; i < 2; i++)
        #pragma unroll
        for (int j = 0; j < 2; j++)
            #pragma unroll
            for (int q = 0; q < 4; q++) acc[i][j][q] = 0.f;

    // staging register buffers
    float4 xv[5];        // A flat window
    float4 bv[3];        // B flat window
    float2 mnext;        // next-chunk mask pair
    float  csqv;         // csq for (p, t)

    // B csq role
    const int pb = tid & 63, tqb = tid >> 6;
    // mask role
    const int mrow = tid >> 2, mseg = tid & 3;

    auto ldg_x = [&](int c) {
        #pragma unroll
        for (int r = 0; r < 5; r++) {
            int idx = tid + 512 * r;
            int row = idx / 20, q = idx - row * 20;
            int goff = c * 80 + 4 * q;
            xv[r] = (goff < KD) ? *(const float4*)(x + (size_t)(b0 + row) * KD + goff)
                                : make_float4(0.f, 0.f, 0.f, 0.f);
        }
    };
    auto ldg_B = [&](int c) {
        #pragma unroll
        for (int r = 0; r < 3; r++) {
            int idx = tid + 512 * r;
            float4 v = make_float4(0.f, 0.f, 0.f, 0.f);
            if (idx < 1280) {
                int p = idx / 20, q = idx - p * 20;
                int goff = c * 80 + 4 * q;
                if (goff < KD) v = *(const float4*)(proto + (size_t)p * KD + goff);
            }
            bv[r] = v;
        }
        int tg = c * TC8 + tqb;
        csqv = (tg < TT) ? g_csq[pb * TT + tg] : 0.f;
    };
    auto ldg_msk = [&](int c) {
        int t = c * TC8 + mseg * 2;
        float m0 = (t     < TT) ? mask[(size_t)(b0 + mrow) * TT + t]     : 0.f;
        float m1 = (t + 1 < TT) ? mask[(size_t)(b0 + mrow) * TT + t + 1] : 0.f;
        mnext = make_float2(m0, m1);
    };
    auto sts_msk = [&](int c) {
        float* ms = msk_s + (c & 1) * MSK_F;
        ms[mrow * 8 + mseg * 2]     = mnext.x;
        ms[mrow * 8 + mseg * 2 + 1] = mnext.y;
        int t = c * TC8 + mseg * 2;
        if (t     < TT) out_mask[(size_t)(b0 + mrow) * TT + t]     = mnext.x;
        if (t + 1 < TT) out_mask[(size_t)(b0 + mrow) * TT + t + 1] = mnext.y;
    };
    auto sts_AB = [&](int c) {
        float* a_s = buf_s + (c & 1) * BUF_F;
        float* b_s = a_s + A_F;
        const float* ms = msk_s + (c & 1) * MSK_F;
        // A: scatter masked tf32 + fused coalesced xcopy
        #pragma unroll
        for (int r = 0; r < 5; r++) {
            int idx = tid + 512 * r;
            int row = idx / 20, q = idx - row * 20;
            int goff = c * 80 + 4 * q;
            if (goff < KD)
                *(float4*)(out_xcopy + (size_t)(b0 + row) * KD + goff) = xv[r];
            float e[4] = {xv[r].x, xv[r].y, xv[r].z, xv[r].w};
            #pragma unroll
            for (int u = 0; u < 4; u++) {
                int off = 4 * q + u;
                int t = off / 10, s = off - 10 * t;
                float m = ms[row * 8 + t];
                a_s[row * TS + t * SLOT + s] = __uint_as_float(tf32r(m * e[u]));
            }
        }
        // B: scatter -2c tf32
        #pragma unroll
        for (int r = 0; r < 3; r++) {
            int idx = tid + 512 * r;
            if (idx < 1280) {
                int p = idx / 20, q = idx - p * 20;
                float e[4] = {bv[r].x, bv[r].y, bv[r].z, bv[r].w};
                #pragma unroll
                for (int u = 0; u < 4; u++) {
                    int off = 4 * q + u;
                    int t = off / 10, s = off - 10 * t;
                    b_s[p * TS + t * SLOT + s] = __uint_as_float(tf32r(-2.f * e[u]));
                }
            }
        }
        // B slots 10/11: csq, 1.0
        b_s[pb * TS + tqb * SLOT + 10] = __uint_as_float(tf32r(csqv));
        b_s[pb * TS + tqb * SLOT + 11] = 1.0f;
    };
    auto slot_fill = [&](int c) {   // A slots 10 (m) and 11 (sum of (m*x~)^2)
        float* a_s = buf_s + (c & 1) * BUF_F;
        const float* ms = msk_s + (c & 1) * MSK_F;
        #pragma unroll
        for (int j = 0; j < 2; j++) {
            int u = tid + 512 * j;
            int row = u >> 3, t = u & 7;
            float* ap = a_s + row * TS + t * SLOT;
            float4 v0 = *(float4*)ap;
            float4 v1 = *(float4*)(ap + 4);
            float2 v2 = *(float2*)(ap + 8);
            float s = v0.x*v0.x + v0.y*v0.y + v0.z*v0.z + v0.w*v0.w
                    + v1.x*v1.x + v1.y*v1.y + v1.z*v1.z + v1.w*v1.w
                    + v2.x*v2.x + v2.y*v2.y;
            ap[10] = ms[row * 8 + t];
            ap[11] = __uint_as_float(tf32r(s));
        }
    };
    auto mma_chunk = [&](int c) {
        const float* a_s = buf_s + (c & 1) * BUF_F;
        const float* b_s = a_s + A_F;
        #pragma unroll
        for (int kc = 0; kc < KCN; kc++) {
            const int k0 = kc * 8;
            uint32_t af[2][4], bf[2][2];
            #pragma unroll
            for (int i = 0; i < 2; i++) {
                int rb = boff + i * 16 + grp;
                af[i][0] = __float_as_uint(a_s[rb * TS + k0 + tig]);
                af[i][1] = __float_as_uint(a_s[(rb + 8) * TS + k0 + tig]);
                af[i][2] = __float_as_uint(a_s[rb * TS + k0 + 4 + tig]);
                af[i][3] = __float_as_uint(a_s[(rb + 8) * TS + k0 + 4 + tig]);
            }
            #pragma unroll
            for (int j = 0; j < 2; j++) {
                int cp2 = noff + j * 8 + grp;
                bf[j][0] = __float_as_uint(b_s[cp2 * TS + k0 + tig]);
                bf[j][1] = __float_as_uint(b_s[cp2 * TS + k0 + 4 + tig]);
            }
            #pragma unroll
            for (int i = 0; i < 2; i++)
                #pragma unroll
                for (int j = 0; j < 2; j++)
                    asm volatile(
                        "mma.sync.aligned.m16n8k8.row.col.f32.tf32.tf32.f32 "
                        "{%0,%1,%2,%3}, {%4,%5,%6,%7}, {%8,%9}, {%0,%1,%2,%3};"
                        : "+f"(acc[i][j][0]), "+f"(acc[i][j][1]),
                          "+f"(acc[i][j][2]), "+f"(acc[i][j][3])
                        : "r"(af[i][0]), "r"(af[i][1]), "r"(af[i][2]), "r"(af[i][3]),
                          "r"(bf[j][0]), "r"(bf[j][1]));
        }
    };

    // preamble: stage mask(c_beg)
    ldg_msk(c_beg);
    sts_msk(c_beg);

    for (int c = c_beg; c < c_end; ++c) {
        ldg_x(c);
        ldg_B(c);
        if (c + 1 < c_end) ldg_msk(c + 1);
        __syncthreads();   // S1: slot_fill(c-1) done -> mma(c-1) safe; buf c&1 free
        if (c + 1 < c_end) sts_msk(c + 1);
        sts_AB(c);
        if (c > c_beg) mma_chunk(c - 1);
        __syncthreads();   // S2: A slots 0..9 of chunk c staged
        slot_fill(c);
    }
    __syncthreads();
    mma_chunk(c_end - 1);

    // epilogue: accumulators -> g_partial (full distances)
    #pragma unroll
    for (int i = 0; i < 2; i++) {
        int rb = b0 + boff + i * 16 + grp;
        #pragma unroll
        for (int j = 0; j < 2; j++) {
            int cc = noff + j * 8 + 2 * tig;
            *(float2*)&g_partial[ks][rb][cc]     = make_float2(acc[i][j][0], acc[i][j][1]);
            *(float2*)&g_partial[ks][rb + 8][cc] = make_float2(acc[i][j][2], acc[i][j][3]);
        }
    }
}

// ---------------- kernel 2: combine, argmin (+exact rescore), outputs, gather ----------------
__global__ void __launch_bounds__(256) finalize_kernel(
    const float* __restrict__ x, const float* __restrict__ mask,
    const float* __restrict__ proto, const int* __restrict__ label,
    float* __restrict__ out_seq, float* __restrict__ out_dist,
    float* __restrict__ out_idx, float* __restrict__ out_label)
{
    __shared__ int s_idx[8];
    const int tid = threadIdx.x, w = tid >> 5, lane = tid & 31;
    const int b = blockIdx.x * 8 + w;

    {
        float d0 = g_partial[0][b][lane]      + g_partial[1][b][lane];
        float d1 = g_partial[0][b][lane + 32] + g_partial[1][b][lane + 32];
        out_dist[(size_t)b * PP + lane]      = d0;
        out_dist[(size_t)b * PP + lane + 32] = d1;

        float bd; int bpick;
        if (d1 < d0) { bd = d1; bpick = lane + 32; } else { bd = d0; bpick = lane; }
        #pragma unroll
        for (int o = 16; o > 0; o >>= 1) {
            float od = __shfl_xor_sync(0xffffffffu, bd, o);
            int   op = __shfl_xor_sync(0xffffffffu, bpick, o);
            if (od < bd || (od == bd && op < bpick)) { bd = od; bpick = op; }
        }
        unsigned c0 = __ballot_sync(0xffffffffu, d0 < bd + MARGIN);
        unsigned c1 = __ballot_sync(0xffffffffu, d1 < bd + MARGIN);
        unsigned long long cm = ((unsigned long long)c1 << 32) | (unsigned long long)c0;
        int idx = bpick;
        if (__popcll(cm) > 1) {
            float best = 3.4e38f; int bi = PP;
            while (cm) {
                int p = __ffsll((long long)cm) - 1;
                cm &= cm - 1;
                float r = 0.f;
                const float* xrow = x + (size_t)b * KD;
                const float* crow = proto + (size_t)p * KD;
                for (int t = lane; t < TT; t += 32) {
                    float m = mask[(size_t)b * TT + t];
                    if (m != 0.f) {
                        const float* xp = xrow + t * DD;
                        const float* cp = crow + t * DD;
                        float dot = 0.f;
                        #pragma unroll
                        for (int d = 0; d < DD; d++) dot = fmaf(xp[d], cp[d], dot);
                        r += g_csq[p * TT + t] - 2.f * dot;
                    }
                }
                #pragma unroll
                for (int o = 16; o > 0; o >>= 1) r += __shfl_xor_sync(0xffffffffu, r, o);
                if (r < best) { best = r; bi = p; }   // ascending p: first-occurrence
            }
            idx = bi;
        }
        if (lane == 0) {
            s_idx[w] = idx;
            out_idx[b]   = (float)idx;
            out_label[b] = (float)label[b];
        }
    }
    __syncthreads();

    const int bbase = blockIdx.x * 8;
    for (int ww = 0; ww < 8; ww++) {
        int idx = s_idx[ww];
        const float4* src = (const float4*)(proto + (size_t)idx * KD);
        float4* dst = (float4*)(out_seq + (size_t)(bbase + ww) * KD);
        for (int i = tid; i < KD / 4; i += 256) dst[i] = src[i];
    }
}

// ---------------- launch ----------------
extern "C" void kernel_launch(void* const* d_in, const int* in_sizes, int n_in,
                              void* d_out, int out_size) {
    const float* x     = (const float*)d_in[0];
    const int*   label = (const int*)d_in[1];
    const float* mask  = (const float*)d_in[2];
    const float* proto = (const float*)d_in[3];
    float* out = (float*)d_out;

    const size_t o_seq   = 0;
    const size_t o_xcopy = (size_t)BB * KD;
    const size_t o_dist  = o_xcopy * 2;
    const size_t o_idx   = o_dist + (size_t)BB * PP;
    const size_t o_label = o_idx + BB;
    const size_t o_mask  = o_label + BB;

    cudaFuncSetAttribute(main_kernel, cudaFuncAttributeMaxDynamicSharedMemorySize, SMEM_MAIN);

    prep_csq<<<(PP * TT + 255) / 256, 256>>>(proto);
    main_kernel<<<NMT * KSPL, 512, SMEM_MAIN>>>(x, mask, proto,
                                                out + o_xcopy, out + o_mask);
    finalize_kernel<<<BB / 8, 256>>>(x, mask, proto, label,
                                     out + o_seq, out + o_dist,
                                     out + o_idx, out + o_label);
}